// round 12
// baseline (speedup 1.0000x reference)
#include <cuda_runtime.h>

// Fully-fused RK4 step of 2D Burgers-type PDE, (8,2,1024,1024) fp32,
// periodic wrap, 4th-order cross stencils (radius 2).
//
// R11 = R8 structure (full-lane tid%W mappings, compile-time 4-row chunks,
// rolling windows, P=k1+2k2 via d_out) + occupancy push:
//   __launch_bounds__(256,4)  -> regs <= 64 (full 64K RF at 4 blocks/SM)
//   PA=88, PB=80, PC=72       -> SMEM 56.6KB <= 57KB/block at 4 blocks/SM
// Target: 32 warps/SM (was 24) to cover LDS/LDG latency in the rolling chains.

#define HW  (1024 * 1024)
#define NB  8
#define TX 64
#define TY 32

#define PA 88
#define PB 80
#define PC 72
#define A_FL (44 * PA)                      // 3872
#define B_FL (40 * PB)                      // 3200
#define SMEM_FLOATS (2 * A_FL + 2 * B_FL)   // 14144
#define SMEM_BYTES  (SMEM_FLOATS * 4)       // 56576

__device__ __forceinline__ float4 ld4(const float* __restrict__ p) {
    return *reinterpret_cast<const float4*>(p);
}
__device__ __forceinline__ float2 ld2(const float* __restrict__ p) {
    return *reinterpret_cast<const float2*>(p);
}
__device__ __forceinline__ void st4(float* __restrict__ p, float a, float b, float c, float d) {
    *reinterpret_cast<float4*>(p) = make_float4(a, b, c, d);
}
__device__ __forceinline__ void put4(float* d, float4 v) {
    d[0] = v.x; d[1] = v.y; d[2] = v.z; d[3] = v.w;
}

// Folded coefficients: a* = nu * lap_tap / dx^2 ; dd* = deriv_tap / dx.
struct Par { float a0, a1, a2, dd1, dd2, UA, UB, VA, VB; };

// Global loader, periodic wrap (fx mult of 4 -> 16B aligned; fe even -> 8B).
struct GL {
    const float* p; int x0, y0;
    __device__ __forceinline__ float4 ld16(int r, int fx) const {
        return ld4(p + (((y0 + r) & 1023) << 10) + ((x0 + fx) & 1023));
    }
    __device__ __forceinline__ float2 ld8(int r, int fe) const {
        return ld2(p + (((y0 + r) & 1023) << 10) + ((x0 + fe) & 1023));
    }
};
// SMEM loader (tile coords, halo offsets baked in).
struct SL {
    const float* s; int pitch, rofs, cofs;
    __device__ __forceinline__ float4 ld16(int r, int fx) const {
        return ld4(s + (r + rofs) * pitch + fx + cofs);
    }
    __device__ __forceinline__ float2 ld8(int r, int fe) const {
        return ld2(s + (r + rofs) * pitch + fe + cofs);
    }
};

// Per-row RHS, 4-wide. e*[8] = {e-2, e-1, e0..e3, e4, e5} (x row values),
// window rows n2,n1,p1,p2 at center 4. Row dir = "x" (H axis) per reference.
__device__ __forceinline__ void rhs_row(
    const float un2[4], const float un1[4], const float ue[8],
    const float up1[4], const float up2[4],
    const float vn2[4], const float vn1[4], const float ve[8],
    const float vp1[4], const float vp2[4],
    const Par& p, float fu[4], float fv[4])
{
#pragma unroll
    for (int j = 0; j < 4; j++) {
        const float uc = ue[j + 2];
        const float vc = ve[j + 2];
        const float lap_u = p.a0 * uc
                          + p.a1 * (un1[j] + up1[j] + ue[j + 1] + ue[j + 3])
                          + p.a2 * (un2[j] + up2[j] + ue[j] + ue[j + 4]);
        const float lap_v = p.a0 * vc
                          + p.a1 * (vn1[j] + vp1[j] + ve[j + 1] + ve[j + 3])
                          + p.a2 * (vn2[j] + vp2[j] + ve[j] + ve[j + 4]);
        const float u_x = p.dd2 * (un2[j] - up2[j]) + p.dd1 * (up1[j] - un1[j]);
        const float v_x = p.dd2 * (vn2[j] - vp2[j]) + p.dd1 * (vp1[j] - vn1[j]);
        const float u_y = p.dd2 * (ue[j] - ue[j + 4]) + p.dd1 * (ue[j + 3] - ue[j + 1]);
        const float v_y = p.dd2 * (ve[j] - ve[j + 4]) + p.dd1 * (ve[j + 3] - ve[j + 1]);
        fu[j] = lap_u + p.UA * uc * u_x + p.UB * vc * u_y;
        fv[j] = lap_v + p.VA * uc * v_x + p.VB * vc * v_y;
    }
}

#define ROT(n2, n1, c, p1, p2) \
    _Pragma("unroll") for (int j = 0; j < 4; j++) { \
        n2[j] = n1[j]; n1[j] = c[j]; c[j] = p1[j]; p1[j] = p2[j]; }

// Rolling column sweep: CHN rows (compile-time) from r0, one float4 column fx.
// emit(r, fu, fv, cu, cv).
template <int CHN, class LU, class LV, class F>
__device__ __forceinline__ void sweep_col(
    const LU& lu, const LV& lv, int fx, int r0, const Par& p, F&& emit)
{
    float un2[4], un1[4], uc[4], up1[4];
    float vn2[4], vn1[4], vc[4], vp1[4];
    put4(un2, lu.ld16(r0 - 2, fx));
    put4(un1, lu.ld16(r0 - 1, fx));
    put4(uc,  lu.ld16(r0,     fx));
    put4(up1, lu.ld16(r0 + 1, fx));
    put4(vn2, lv.ld16(r0 - 2, fx));
    put4(vn1, lv.ld16(r0 - 1, fx));
    put4(vc,  lv.ld16(r0,     fx));
    put4(vp1, lv.ld16(r0 + 1, fx));
#pragma unroll
    for (int i = 0; i < CHN; i++) {
        const int r = r0 + i;
        float up2[4], vp2[4];
        put4(up2, lu.ld16(r + 2, fx));
        put4(vp2, lv.ld16(r + 2, fx));
        const float2 uL = lu.ld8(r, fx - 2), uR = lu.ld8(r, fx + 4);
        const float2 vL = lv.ld8(r, fx - 2), vR = lv.ld8(r, fx + 4);
        float ue[8] = {uL.x, uL.y, uc[0], uc[1], uc[2], uc[3], uR.x, uR.y};
        float ve[8] = {vL.x, vL.y, vc[0], vc[1], vc[2], vc[3], vR.x, vR.y};
        float fu[4], fv[4];
        rhs_row(un2, un1, ue, up1, up2, vn2, vn1, ve, vp1, vp2, p, fu, fv);
        emit(r, fu, fv, uc, vc);
        ROT(un2, un1, uc, up1, up2);
        ROT(vn2, vn1, vc, vp1, vp2);
    }
}

__global__ __launch_bounds__(256, 4) void rk4_fused_kernel(
    const float* __restrict__ h,
    float* __restrict__ out,
    const float* __restrict__ pRe,
    const float* __restrict__ pUA,
    const float* __restrict__ pUB,
    const float* __restrict__ pVA,
    const float* __restrict__ pVB)
{
    extern __shared__ float smem[];
    float* uA = smem;
    float* vA = uA + A_FL;
    float* uB = vA + A_FL;
    float* vB = uB + B_FL;

    const int tid  = threadIdx.x;
    const int x0   = blockIdx.x * TX;
    const int y0   = blockIdx.y * TY;
    const int base = blockIdx.z * 2 * HW;

    const float nu = 0.001f / pRe[0];
    const Par p = { nu * -50000.0f,
                    nu * (40000.0f / 3.0f),
                    nu * (-10000.0f / 12.0f),
                    800.0f / 12.0f,
                    100.0f / 12.0f,
                    pUA[0], pUB[0], pVA[0], pVB[0] };

    const GL glu{h + base,      x0, y0};
    const GL glv{h + base + HW, x0, y0};

    // ===== stage 1: k1 from h; s1 = h + 0.25*k1 -> A
    //        (22 cols -3..18, rows -6..37; 11 chunks h=4, 242 thr)
    if (tid < 242) {
        const int cc = tid % 22;
        const int ch = tid / 22;
        const int fx = 4 * (cc - 3);
        const int r0 = -6 + 4 * ch;
        sweep_col<4>(glu, glv, fx, r0, p,
            [&](int r, const float fu[4], const float fv[4],
                const float cu[4], const float cv[4]) {
                const int ix = (r + 6) * PA + fx + 12;
                st4(uA + ix, cu[0] + 0.25f * fu[0], cu[1] + 0.25f * fu[1],
                             cu[2] + 0.25f * fu[2], cu[3] + 0.25f * fu[3]);
                st4(vA + ix, cv[0] + 0.25f * fv[0], cv[1] + 0.25f * fv[1],
                             cv[2] + 0.25f * fv[2], cv[3] + 0.25f * fv[3]);
            });
    }
    __syncthreads();

    // ===== stage 2: k2 from s1(A); s2 -> B; P = k1 + 2*k2 -> out
    //        (20 cols -2..17, rows -4..35; 10 chunks h=4, 200 thr)
    if (tid < 200) {
        const int cc = tid % 20;
        const int ch = tid / 20;
        const int c  = cc - 2;
        const int fx = 4 * c;
        const int r0 = -4 + 4 * ch;
        const SL alu{uA, PA, 6, 12};
        const SL alv{vA, PA, 6, 12};
        sweep_col<4>(alu, alv, fx, r0, p,
            [&](int r, const float fu[4], const float fv[4],
                const float cu[4], const float cv[4]) {
                float hu4[4], hv4[4];
                put4(hu4, glu.ld16(r, fx));
                put4(hv4, glv.ld16(r, fx));
                const int ix = (r + 4) * PB + fx + 8;
                st4(uB + ix, hu4[0] + 0.25f * fu[0], hu4[1] + 0.25f * fu[1],
                             hu4[2] + 0.25f * fu[2], hu4[3] + 0.25f * fu[3]);
                st4(vB + ix, hv4[0] + 0.25f * fv[0], hv4[1] + 0.25f * fv[1],
                             hv4[2] + 0.25f * fv[2], hv4[3] + 0.25f * fv[3]);
                if ((unsigned)c < 16u && (unsigned)r < 32u) {
                    // k1 = 4*(s1c - h); P = k1 + 2*k2
                    const int off = base + ((y0 + r) << 10) + x0 + fx;
                    st4(out + off,
                        4.0f * (cu[0] - hu4[0]) + 2.0f * fu[0],
                        4.0f * (cu[1] - hu4[1]) + 2.0f * fu[1],
                        4.0f * (cu[2] - hu4[2]) + 2.0f * fu[2],
                        4.0f * (cu[3] - hu4[3]) + 2.0f * fu[3]);
                    st4(out + off + HW,
                        4.0f * (cv[0] - hv4[0]) + 2.0f * fv[0],
                        4.0f * (cv[1] - hv4[1]) + 2.0f * fv[1],
                        4.0f * (cv[2] - hv4[2]) + 2.0f * fv[2],
                        4.0f * (cv[3] - hv4[3]) + 2.0f * fv[3]);
                }
            });
    }
    __syncthreads();

    // ===== stage 3: k3 from s2(B); s3 = h + 0.5*k3 -> A storage (C layout)
    //        (18 cols -1..16, rows -2..33; 9 chunks h=4, 162 thr)
    if (tid < 162) {
        const int cc = tid % 18;
        const int ch = tid / 18;
        const int fx = 4 * (cc - 1);
        const int r0 = -2 + 4 * ch;
        const SL blu{uB, PB, 4, 8};
        const SL blv{vB, PB, 4, 8};
        sweep_col<4>(blu, blv, fx, r0, p,
            [&](int r, const float fu[4], const float fv[4],
                const float cu[4], const float cv[4]) {
                float hu4[4], hv4[4];
                put4(hu4, glu.ld16(r, fx));
                put4(hv4, glv.ld16(r, fx));
                const int ix = (r + 2) * PC + fx + 4;
                st4(uA + ix, hu4[0] + 0.5f * fu[0], hu4[1] + 0.5f * fu[1],
                             hu4[2] + 0.5f * fu[2], hu4[3] + 0.5f * fu[3]);
                st4(vA + ix, hv4[0] + 0.5f * fv[0], hv4[1] + 0.5f * fv[1],
                             hv4[2] + 0.5f * fv[2], hv4[3] + 0.5f * fv[3]);
            });
    }
    __syncthreads();

    // ===== stage 4: k4 from s3(C); out = h + (DT/6)*(P + 2*k3 + k4)
    //        (16 cols 0..15, rows 0..31; 16 chunks h=2, 256 thr)
    {
        const int cc = tid & 15;
        const int ch = tid >> 4;
        const int fx = 4 * cc;
        const int r0 = 2 * ch;
        const SL clu{uA, PC, 2, 4};
        const SL clv{vA, PC, 2, 4};
        const float w6 = 0.5f / 6.0f;
        sweep_col<2>(clu, clv, fx, r0, p,
            [&](int r, const float fu[4], const float fv[4],
                const float cu[4], const float cv[4]) {
                float hu4[4], hv4[4];
                put4(hu4, glu.ld16(r, fx));
                put4(hv4, glv.ld16(r, fx));
                const int off = base + ((y0 + r) << 10) + x0 + fx;
                float Pu[4], Pv[4];
                put4(Pu, ld4(out + off));
                put4(Pv, ld4(out + off + HW));
                // 2*k3 = 4*(s3c - h)
                st4(out + off,
                    hu4[0] + w6 * (Pu[0] + 4.0f * (cu[0] - hu4[0]) + fu[0]),
                    hu4[1] + w6 * (Pu[1] + 4.0f * (cu[1] - hu4[1]) + fu[1]),
                    hu4[2] + w6 * (Pu[2] + 4.0f * (cu[2] - hu4[2]) + fu[2]),
                    hu4[3] + w6 * (Pu[3] + 4.0f * (cu[3] - hu4[3]) + fu[3]));
                st4(out + off + HW,
                    hv4[0] + w6 * (Pv[0] + 4.0f * (cv[0] - hv4[0]) + fv[0]),
                    hv4[1] + w6 * (Pv[1] + 4.0f * (cv[1] - hv4[1]) + fv[1]),
                    hv4[2] + w6 * (Pv[2] + 4.0f * (cv[2] - hv4[2]) + fv[2]),
                    hv4[3] + w6 * (Pv[3] + 4.0f * (cv[3] - hv4[3]) + fv[3]));
            });
    }
}

extern "C" void kernel_launch(void* const* d_in, const int* in_sizes, int n_in,
                              void* d_out, int out_size)
{
    const float* h = nullptr;
    const float* sc[5] = {nullptr, nullptr, nullptr, nullptr, nullptr};
    int nsc = 0;
    for (int i = 0; i < n_in; i++) {
        if (in_sizes[i] == NB * 2 * HW) {
            h = (const float*)d_in[i];
        } else if (nsc < 5) {
            sc[nsc++] = (const float*)d_in[i];
        }
    }
    const float* Re = sc[0];
    const float* UA = sc[1];
    const float* UB = sc[2];
    const float* VA = sc[3];
    const float* VB = sc[4];

    static bool attr_done = false;
    if (!attr_done) {
        cudaFuncSetAttribute(rk4_fused_kernel,
                             cudaFuncAttributeMaxDynamicSharedMemorySize, SMEM_BYTES);
        attr_done = true;
    }

    dim3 grid(1024 / TX, 1024 / TY, NB);    // 16 x 32 x 8 = 4096 blocks
    rk4_fused_kernel<<<grid, 256, SMEM_BYTES>>>(h, (float*)d_out, Re, UA, UB, VA, VB);
    (void)out_size;
}

// round 13
// speedup vs baseline: 1.0013x; 1.0013x over previous
#include <cuda_runtime.h>

// Fully-fused RK4 step of 2D Burgers-type PDE, (8,2,1024,1024) fp32,
// periodic wrap, 4th-order cross stencils (radius 2).
//
// R12 = R7 skeleton (full-lane tid%W mappings, scalar FFMA, rolling 5-row
// windows, pitches 92/84/76, 3 blocks/SM) plus:
//  - P = k1+2*k2 kept in SMEM (not round-tripped through d_out)
//  - advective coefficients folded into derivative taps (16 fewer FFMA/point)
//  - stage 3 rebalanced to 216 active threads (h=3 chunks)

#define HW  (1024 * 1024)
#define NB  8
#define TX 64
#define TY 32

#define PA 92
#define PB 84
#define PC 76
#define PP 68                               // P buffer pitch (32 rows x 64 cols)
#define A_FL (44 * PA)                      // 4048
#define B_FL (40 * PB)                      // 3360
#define P_FL (32 * PP)                      // 2176
#define SMEM_FLOATS (2 * A_FL + 2 * B_FL + 2 * P_FL)   // 19168
#define SMEM_BYTES  (SMEM_FLOATS * 4)                  // 76672 (74.9 KB)

__device__ __forceinline__ float4 ld4(const float* __restrict__ p) {
    return *reinterpret_cast<const float4*>(p);
}
__device__ __forceinline__ float2 ld2(const float* __restrict__ p) {
    return *reinterpret_cast<const float2*>(p);
}
__device__ __forceinline__ void st4(float* __restrict__ p, float a, float b, float c, float d) {
    *reinterpret_cast<float4*>(p) = make_float4(a, b, c, d);
}
__device__ __forceinline__ void put4(float* d, float4 v) {
    d[0] = v.x; d[1] = v.y; d[2] = v.z; d[3] = v.w;
}

// a*  = nu * lap_tap / dx^2
// xad = X * deriv_tap / dx  (advective coefficient folded into the tap)
struct Par {
    float a0, a1, a2;
    float uad1, uad2, ubd1, ubd2;
    float vad1, vad2, vbd1, vbd2;
};

// Global loader, periodic wrap (fx mult of 4 -> 16B aligned; fe even -> 8B).
struct GL {
    const float* p; int x0, y0;
    __device__ __forceinline__ float4 ld16(int r, int fx) const {
        return ld4(p + (((y0 + r) & 1023) << 10) + ((x0 + fx) & 1023));
    }
    __device__ __forceinline__ float2 ld8(int r, int fe) const {
        return ld2(p + (((y0 + r) & 1023) << 10) + ((x0 + fe) & 1023));
    }
};
// SMEM loader (tile coords, halo offsets baked in).
struct SL {
    const float* s; int pitch, rofs, cofs;
    __device__ __forceinline__ float4 ld16(int r, int fx) const {
        return ld4(s + (r + rofs) * pitch + fx + cofs);
    }
    __device__ __forceinline__ float2 ld8(int r, int fe) const {
        return ld2(s + (r + rofs) * pitch + fe + cofs);
    }
};

// Per-row RHS, 4-wide. e*[8] = {e-2, e-1, e0..e3, e4, e5} (x row values),
// window rows n2,n1,p1,p2 at center 4. Row dir = "x" (H axis) per reference.
__device__ __forceinline__ void rhs_row(
    const float un2[4], const float un1[4], const float ue[8],
    const float up1[4], const float up2[4],
    const float vn2[4], const float vn1[4], const float ve[8],
    const float vp1[4], const float vp2[4],
    const Par& p, float fu[4], float fv[4])
{
#pragma unroll
    for (int j = 0; j < 4; j++) {
        const float uc = ue[j + 2];
        const float vc = ve[j + 2];
        const float lap_u = p.a0 * uc
                          + p.a1 * (un1[j] + up1[j] + ue[j + 1] + ue[j + 3])
                          + p.a2 * (un2[j] + up2[j] + ue[j] + ue[j + 4]);
        const float lap_v = p.a0 * vc
                          + p.a1 * (vn1[j] + vp1[j] + ve[j + 1] + ve[j + 3])
                          + p.a2 * (vn2[j] + vp2[j] + ve[j] + ve[j + 4]);
        // scaled derivatives (advective coefficient folded into taps)
        const float uxs = p.uad2 * (un2[j] - up2[j]) + p.uad1 * (up1[j] - un1[j]);
        const float vxs = p.vad2 * (vn2[j] - vp2[j]) + p.vad1 * (vp1[j] - vn1[j]);
        const float uys = p.ubd2 * (ue[j] - ue[j + 4]) + p.ubd1 * (ue[j + 3] - ue[j + 1]);
        const float vys = p.vbd2 * (ve[j] - ve[j + 4]) + p.vbd1 * (ve[j + 3] - ve[j + 1]);
        fu[j] = lap_u + uc * uxs + vc * uys;
        fv[j] = lap_v + uc * vxs + vc * vys;
    }
}

#define ROT(n2, n1, c, p1, p2) \
    _Pragma("unroll") for (int j = 0; j < 4; j++) { \
        n2[j] = n1[j]; n1[j] = c[j]; c[j] = p1[j]; p1[j] = p2[j]; }

// Rolling column sweep: CHN rows (compile-time) from r0, one float4 column fx.
// emit(r, fu, fv, cu, cv).
template <int CHN, class LU, class LV, class F>
__device__ __forceinline__ void sweep_col(
    const LU& lu, const LV& lv, int fx, int r0, const Par& p, F&& emit)
{
    float un2[4], un1[4], uc[4], up1[4];
    float vn2[4], vn1[4], vc[4], vp1[4];
    put4(un2, lu.ld16(r0 - 2, fx));
    put4(un1, lu.ld16(r0 - 1, fx));
    put4(uc,  lu.ld16(r0,     fx));
    put4(up1, lu.ld16(r0 + 1, fx));
    put4(vn2, lv.ld16(r0 - 2, fx));
    put4(vn1, lv.ld16(r0 - 1, fx));
    put4(vc,  lv.ld16(r0,     fx));
    put4(vp1, lv.ld16(r0 + 1, fx));
#pragma unroll
    for (int i = 0; i < CHN; i++) {
        const int r = r0 + i;
        float up2[4], vp2[4];
        put4(up2, lu.ld16(r + 2, fx));
        put4(vp2, lv.ld16(r + 2, fx));
        const float2 uL = lu.ld8(r, fx - 2), uR = lu.ld8(r, fx + 4);
        const float2 vL = lv.ld8(r, fx - 2), vR = lv.ld8(r, fx + 4);
        float ue[8] = {uL.x, uL.y, uc[0], uc[1], uc[2], uc[3], uR.x, uR.y};
        float ve[8] = {vL.x, vL.y, vc[0], vc[1], vc[2], vc[3], vR.x, vR.y};
        float fu[4], fv[4];
        rhs_row(un2, un1, ue, up1, up2, vn2, vn1, ve, vp1, vp2, p, fu, fv);
        emit(r, fu, fv, uc, vc);
        ROT(un2, un1, uc, up1, up2);
        ROT(vn2, vn1, vc, vp1, vp2);
    }
}

__global__ __launch_bounds__(256, 3) void rk4_fused_kernel(
    const float* __restrict__ h,
    float* __restrict__ out,
    const float* __restrict__ pRe,
    const float* __restrict__ pUA,
    const float* __restrict__ pUB,
    const float* __restrict__ pVA,
    const float* __restrict__ pVB)
{
    extern __shared__ float smem[];
    float* uA = smem;
    float* vA = uA + A_FL;
    float* uB = vA + A_FL;
    float* vB = uB + B_FL;
    float* uP = vB + B_FL;
    float* vP = uP + P_FL;

    const int tid  = threadIdx.x;
    const int x0   = blockIdx.x * TX;
    const int y0   = blockIdx.y * TY;
    const int base = blockIdx.z * 2 * HW;

    const float nu = 0.001f / pRe[0];
    const float d1 = 800.0f / 12.0f, d2 = 100.0f / 12.0f;
    const float UA = pUA[0], UB = pUB[0], VA = pVA[0], VB = pVB[0];
    const Par p = { nu * -50000.0f,
                    nu * (40000.0f / 3.0f),
                    nu * (-10000.0f / 12.0f),
                    UA * d1, UA * d2, UB * d1, UB * d2,
                    VA * d1, VA * d2, VB * d1, VB * d2 };

    const GL glu{h + base,      x0, y0};
    const GL glv{h + base + HW, x0, y0};

    // ===== stage 1: k1 from h; s1 = h + 0.25*k1 -> A
    //        (22 cols -3..18, rows -6..37; 11 chunks h=4, 242 thr)
    if (tid < 242) {
        const int cc = tid % 22;
        const int ch = tid / 22;
        const int fx = 4 * (cc - 3);
        const int r0 = -6 + 4 * ch;
        sweep_col<4>(glu, glv, fx, r0, p,
            [&](int r, const float fu[4], const float fv[4],
                const float cu[4], const float cv[4]) {
                const int ix = (r + 6) * PA + fx + 12;
                st4(uA + ix, cu[0] + 0.25f * fu[0], cu[1] + 0.25f * fu[1],
                             cu[2] + 0.25f * fu[2], cu[3] + 0.25f * fu[3]);
                st4(vA + ix, cv[0] + 0.25f * fv[0], cv[1] + 0.25f * fv[1],
                             cv[2] + 0.25f * fv[2], cv[3] + 0.25f * fv[3]);
            });
    }
    __syncthreads();

    // ===== stage 2: k2 from s1(A); s2 = h + 0.25*k2 -> B; P = k1+2k2 -> SMEM
    //        (20 cols -2..17, rows -4..35; 10 chunks h=4, 200 thr)
    if (tid < 200) {
        const int cc = tid % 20;
        const int ch = tid / 20;
        const int c  = cc - 2;
        const int fx = 4 * c;
        const int r0 = -4 + 4 * ch;
        const SL alu{uA, PA, 6, 12};
        const SL alv{vA, PA, 6, 12};
        sweep_col<4>(alu, alv, fx, r0, p,
            [&](int r, const float fu[4], const float fv[4],
                const float cu[4], const float cv[4]) {
                float hu4[4], hv4[4];
                put4(hu4, glu.ld16(r, fx));
                put4(hv4, glv.ld16(r, fx));
                const int ix = (r + 4) * PB + fx + 8;
                st4(uB + ix, hu4[0] + 0.25f * fu[0], hu4[1] + 0.25f * fu[1],
                             hu4[2] + 0.25f * fu[2], hu4[3] + 0.25f * fu[3]);
                st4(vB + ix, hv4[0] + 0.25f * fv[0], hv4[1] + 0.25f * fv[1],
                             hv4[2] + 0.25f * fv[2], hv4[3] + 0.25f * fv[3]);
                if ((unsigned)c < 16u && (unsigned)r < 32u) {
                    // k1 = 4*(s1c - h); P = k1 + 2*k2
                    const int px = r * PP + fx;
                    st4(uP + px,
                        4.0f * (cu[0] - hu4[0]) + 2.0f * fu[0],
                        4.0f * (cu[1] - hu4[1]) + 2.0f * fu[1],
                        4.0f * (cu[2] - hu4[2]) + 2.0f * fu[2],
                        4.0f * (cu[3] - hu4[3]) + 2.0f * fu[3]);
                    st4(vP + px,
                        4.0f * (cv[0] - hv4[0]) + 2.0f * fv[0],
                        4.0f * (cv[1] - hv4[1]) + 2.0f * fv[1],
                        4.0f * (cv[2] - hv4[2]) + 2.0f * fv[2],
                        4.0f * (cv[3] - hv4[3]) + 2.0f * fv[3]);
                }
            });
    }
    __syncthreads();

    // ===== stage 3: k3 from s2(B); s3 = h + 0.5*k3 -> A storage (C layout)
    //        (18 cols -1..16, rows -2..33; 12 chunks h=3, 216 thr)
    if (tid < 216) {
        const int cc = tid % 18;
        const int ch = tid / 18;
        const int fx = 4 * (cc - 1);
        const int r0 = -2 + 3 * ch;
        const SL blu{uB, PB, 4, 8};
        const SL blv{vB, PB, 4, 8};
        sweep_col<3>(blu, blv, fx, r0, p,
            [&](int r, const float fu[4], const float fv[4],
                const float cu[4], const float cv[4]) {
                float hu4[4], hv4[4];
                put4(hu4, glu.ld16(r, fx));
                put4(hv4, glv.ld16(r, fx));
                const int ix = (r + 2) * PC + fx + 4;
                st4(uA + ix, hu4[0] + 0.5f * fu[0], hu4[1] + 0.5f * fu[1],
                             hu4[2] + 0.5f * fu[2], hu4[3] + 0.5f * fu[3]);
                st4(vA + ix, hv4[0] + 0.5f * fv[0], hv4[1] + 0.5f * fv[1],
                             hv4[2] + 0.5f * fv[2], hv4[3] + 0.5f * fv[3]);
            });
    }
    __syncthreads();

    // ===== stage 4: k4 from s3(C); out = h + (DT/6)*(P + 2*k3 + k4)
    //        (16 cols 0..15, rows 0..31; 16 chunks h=2, 256 thr)
    {
        const int cc = tid & 15;
        const int ch = tid >> 4;
        const int fx = 4 * cc;
        const int r0 = 2 * ch;
        const SL clu{uA, PC, 2, 4};
        const SL clv{vA, PC, 2, 4};
        const float w6 = 0.5f / 6.0f;
        sweep_col<2>(clu, clv, fx, r0, p,
            [&](int r, const float fu[4], const float fv[4],
                const float cu[4], const float cv[4]) {
                float hu4[4], hv4[4];
                put4(hu4, glu.ld16(r, fx));
                put4(hv4, glv.ld16(r, fx));
                const int px  = r * PP + fx;
                const int off = base + ((y0 + r) << 10) + x0 + fx;
                float Pu[4], Pv[4];
                put4(Pu, ld4(uP + px));
                put4(Pv, ld4(vP + px));
                // 2*k3 = 4*(s3c - h)
                st4(out + off,
                    hu4[0] + w6 * (Pu[0] + 4.0f * (cu[0] - hu4[0]) + fu[0]),
                    hu4[1] + w6 * (Pu[1] + 4.0f * (cu[1] - hu4[1]) + fu[1]),
                    hu4[2] + w6 * (Pu[2] + 4.0f * (cu[2] - hu4[2]) + fu[2]),
                    hu4[3] + w6 * (Pu[3] + 4.0f * (cu[3] - hu4[3]) + fu[3]));
                st4(out + off + HW,
                    hv4[0] + w6 * (Pv[0] + 4.0f * (cv[0] - hv4[0]) + fv[0]),
                    hv4[1] + w6 * (Pv[1] + 4.0f * (cv[1] - hv4[1]) + fv[1]),
                    hv4[2] + w6 * (Pv[2] + 4.0f * (cv[2] - hv4[2]) + fv[2]),
                    hv4[3] + w6 * (Pv[3] + 4.0f * (cv[3] - hv4[3]) + fv[3]));
            });
    }
}

extern "C" void kernel_launch(void* const* d_in, const int* in_sizes, int n_in,
                              void* d_out, int out_size)
{
    const float* h = nullptr;
    const float* sc[5] = {nullptr, nullptr, nullptr, nullptr, nullptr};
    int nsc = 0;
    for (int i = 0; i < n_in; i++) {
        if (in_sizes[i] == NB * 2 * HW) {
            h = (const float*)d_in[i];
        } else if (nsc < 5) {
            sc[nsc++] = (const float*)d_in[i];
        }
    }
    const float* Re = sc[0];
    const float* UA = sc[1];
    const float* UB = sc[2];
    const float* VA = sc[3];
    const float* VB = sc[4];

    static bool attr_done = false;
    if (!attr_done) {
        cudaFuncSetAttribute(rk4_fused_kernel,
                             cudaFuncAttributeMaxDynamicSharedMemorySize, SMEM_BYTES);
        attr_done = true;
    }

    dim3 grid(1024 / TX, 1024 / TY, NB);    // 16 x 32 x 8 = 4096 blocks
    rk4_fused_kernel<<<grid, 256, SMEM_BYTES>>>(h, (float*)d_out, Re, UA, UB, VA, VB);
    (void)out_size;
}

// round 14
// speedup vs baseline: 1.1512x; 1.1497x over previous
#include <cuda_runtime.h>

// Fully-fused RK4 step of 2D Burgers-type PDE, (8,2,1024,1024) fp32,
// periodic wrap, 4th-order cross stencils (radius 2).
//
// R13 = R8 skeleton (full-lane tid%W mappings, rolling 5-row windows,
// ld8 side loads, P = k1+2k2 via d_out, 3 blocks/SM) with:
//  - scalar FFMA math (f32x2 reverted: measured wash + alu cost)
//  - advective coefficients folded into derivative taps (-16 FFMA/point)
//  - pitches 88/80/72 -> SMEM 56.6KB/block = 170KB/SM, preserving ~58KB L1D
//    (R12 lesson: SMEM footprint evicts the L1D serving h reloads)
//  - stage 3 rebalanced to h=3 chunks (216 active threads)

#define HW  (1024 * 1024)
#define NB  8
#define TX 64
#define TY 32

#define PA 88
#define PB 80
#define PC 72
#define A_FL (44 * PA)                      // 3872
#define B_FL (40 * PB)                      // 3200
#define SMEM_FLOATS (2 * A_FL + 2 * B_FL)   // 14144
#define SMEM_BYTES  (SMEM_FLOATS * 4)       // 56576

__device__ __forceinline__ float4 ld4(const float* __restrict__ p) {
    return *reinterpret_cast<const float4*>(p);
}
__device__ __forceinline__ float2 ld2(const float* __restrict__ p) {
    return *reinterpret_cast<const float2*>(p);
}
__device__ __forceinline__ void st4(float* __restrict__ p, float a, float b, float c, float d) {
    *reinterpret_cast<float4*>(p) = make_float4(a, b, c, d);
}
__device__ __forceinline__ void put4(float* d, float4 v) {
    d[0] = v.x; d[1] = v.y; d[2] = v.z; d[3] = v.w;
}

// a* = nu * lap_tap / dx^2 ; xad = X * deriv_tap / dx (advective folded).
struct Par {
    float a0, a1, a2;
    float uad1, uad2, ubd1, ubd2;
    float vad1, vad2, vbd1, vbd2;
};

// Global loader, periodic wrap (fx mult of 4 -> 16B aligned; fe even -> 8B).
struct GL {
    const float* p; int x0, y0;
    __device__ __forceinline__ float4 ld16(int r, int fx) const {
        return ld4(p + (((y0 + r) & 1023) << 10) + ((x0 + fx) & 1023));
    }
    __device__ __forceinline__ float2 ld8(int r, int fe) const {
        return ld2(p + (((y0 + r) & 1023) << 10) + ((x0 + fe) & 1023));
    }
};
// SMEM loader (tile coords, halo offsets baked in).
struct SL {
    const float* s; int pitch, rofs, cofs;
    __device__ __forceinline__ float4 ld16(int r, int fx) const {
        return ld4(s + (r + rofs) * pitch + fx + cofs);
    }
    __device__ __forceinline__ float2 ld8(int r, int fe) const {
        return ld2(s + (r + rofs) * pitch + fe + cofs);
    }
};

// Per-row RHS, 4-wide. e*[8] = {e-2, e-1, e0..e3, e4, e5} (x row values),
// window rows n2,n1,p1,p2 at center 4. Row dir = "x" (H axis) per reference.
__device__ __forceinline__ void rhs_row(
    const float un2[4], const float un1[4], const float ue[8],
    const float up1[4], const float up2[4],
    const float vn2[4], const float vn1[4], const float ve[8],
    const float vp1[4], const float vp2[4],
    const Par& p, float fu[4], float fv[4])
{
#pragma unroll
    for (int j = 0; j < 4; j++) {
        const float uc = ue[j + 2];
        const float vc = ve[j + 2];
        const float lap_u = p.a0 * uc
                          + p.a1 * (un1[j] + up1[j] + ue[j + 1] + ue[j + 3])
                          + p.a2 * (un2[j] + up2[j] + ue[j] + ue[j + 4]);
        const float lap_v = p.a0 * vc
                          + p.a1 * (vn1[j] + vp1[j] + ve[j + 1] + ve[j + 3])
                          + p.a2 * (vn2[j] + vp2[j] + ve[j] + ve[j + 4]);
        const float uxs = p.uad2 * (un2[j] - up2[j]) + p.uad1 * (up1[j] - un1[j]);
        const float vxs = p.vad2 * (vn2[j] - vp2[j]) + p.vad1 * (vp1[j] - vn1[j]);
        const float uys = p.ubd2 * (ue[j] - ue[j + 4]) + p.ubd1 * (ue[j + 3] - ue[j + 1]);
        const float vys = p.vbd2 * (ve[j] - ve[j + 4]) + p.vbd1 * (ve[j + 3] - ve[j + 1]);
        fu[j] = lap_u + uc * uxs + vc * uys;
        fv[j] = lap_v + uc * vxs + vc * vys;
    }
}

#define ROT(n2, n1, c, p1, p2) \
    _Pragma("unroll") for (int j = 0; j < 4; j++) { \
        n2[j] = n1[j]; n1[j] = c[j]; c[j] = p1[j]; p1[j] = p2[j]; }

// Rolling column sweep: CHN rows (compile-time) from r0, one float4 column fx.
// emit(r, fu, fv, cu, cv).
template <int CHN, class LU, class LV, class F>
__device__ __forceinline__ void sweep_col(
    const LU& lu, const LV& lv, int fx, int r0, const Par& p, F&& emit)
{
    float un2[4], un1[4], uc[4], up1[4];
    float vn2[4], vn1[4], vc[4], vp1[4];
    put4(un2, lu.ld16(r0 - 2, fx));
    put4(un1, lu.ld16(r0 - 1, fx));
    put4(uc,  lu.ld16(r0,     fx));
    put4(up1, lu.ld16(r0 + 1, fx));
    put4(vn2, lv.ld16(r0 - 2, fx));
    put4(vn1, lv.ld16(r0 - 1, fx));
    put4(vc,  lv.ld16(r0,     fx));
    put4(vp1, lv.ld16(r0 + 1, fx));
#pragma unroll
    for (int i = 0; i < CHN; i++) {
        const int r = r0 + i;
        float up2[4], vp2[4];
        put4(up2, lu.ld16(r + 2, fx));
        put4(vp2, lv.ld16(r + 2, fx));
        const float2 uL = lu.ld8(r, fx - 2), uR = lu.ld8(r, fx + 4);
        const float2 vL = lv.ld8(r, fx - 2), vR = lv.ld8(r, fx + 4);
        float ue[8] = {uL.x, uL.y, uc[0], uc[1], uc[2], uc[3], uR.x, uR.y};
        float ve[8] = {vL.x, vL.y, vc[0], vc[1], vc[2], vc[3], vR.x, vR.y};
        float fu[4], fv[4];
        rhs_row(un2, un1, ue, up1, up2, vn2, vn1, ve, vp1, vp2, p, fu, fv);
        emit(r, fu, fv, uc, vc);
        ROT(un2, un1, uc, up1, up2);
        ROT(vn2, vn1, vc, vp1, vp2);
    }
}

__global__ __launch_bounds__(256, 3) void rk4_fused_kernel(
    const float* __restrict__ h,
    float* __restrict__ out,
    const float* __restrict__ pRe,
    const float* __restrict__ pUA,
    const float* __restrict__ pUB,
    const float* __restrict__ pVA,
    const float* __restrict__ pVB)
{
    extern __shared__ float smem[];
    float* uA = smem;
    float* vA = uA + A_FL;
    float* uB = vA + A_FL;
    float* vB = uB + B_FL;

    const int tid  = threadIdx.x;
    const int x0   = blockIdx.x * TX;
    const int y0   = blockIdx.y * TY;
    const int base = blockIdx.z * 2 * HW;

    const float nu = 0.001f / pRe[0];
    const float d1 = 800.0f / 12.0f, d2 = 100.0f / 12.0f;
    const float UA = pUA[0], UB = pUB[0], VA = pVA[0], VB = pVB[0];
    const Par p = { nu * -50000.0f,
                    nu * (40000.0f / 3.0f),
                    nu * (-10000.0f / 12.0f),
                    UA * d1, UA * d2, UB * d1, UB * d2,
                    VA * d1, VA * d2, VB * d1, VB * d2 };

    const GL glu{h + base,      x0, y0};
    const GL glv{h + base + HW, x0, y0};

    // ===== stage 1: k1 from h; s1 = h + 0.25*k1 -> A
    //        (22 cols -3..18, rows -6..37; 11 chunks h=4, 242 thr)
    if (tid < 242) {
        const int cc = tid % 22;
        const int ch = tid / 22;
        const int fx = 4 * (cc - 3);
        const int r0 = -6 + 4 * ch;
        sweep_col<4>(glu, glv, fx, r0, p,
            [&](int r, const float fu[4], const float fv[4],
                const float cu[4], const float cv[4]) {
                const int ix = (r + 6) * PA + fx + 12;
                st4(uA + ix, cu[0] + 0.25f * fu[0], cu[1] + 0.25f * fu[1],
                             cu[2] + 0.25f * fu[2], cu[3] + 0.25f * fu[3]);
                st4(vA + ix, cv[0] + 0.25f * fv[0], cv[1] + 0.25f * fv[1],
                             cv[2] + 0.25f * fv[2], cv[3] + 0.25f * fv[3]);
            });
    }
    __syncthreads();

    // ===== stage 2: k2 from s1(A); s2 = h + 0.25*k2 -> B; P = k1+2k2 -> out
    //        (20 cols -2..17, rows -4..35; 10 chunks h=4, 200 thr)
    if (tid < 200) {
        const int cc = tid % 20;
        const int ch = tid / 20;
        const int c  = cc - 2;
        const int fx = 4 * c;
        const int r0 = -4 + 4 * ch;
        const SL alu{uA, PA, 6, 12};
        const SL alv{vA, PA, 6, 12};
        sweep_col<4>(alu, alv, fx, r0, p,
            [&](int r, const float fu[4], const float fv[4],
                const float cu[4], const float cv[4]) {
                float hu4[4], hv4[4];
                put4(hu4, glu.ld16(r, fx));
                put4(hv4, glv.ld16(r, fx));
                const int ix = (r + 4) * PB + fx + 8;
                st4(uB + ix, hu4[0] + 0.25f * fu[0], hu4[1] + 0.25f * fu[1],
                             hu4[2] + 0.25f * fu[2], hu4[3] + 0.25f * fu[3]);
                st4(vB + ix, hv4[0] + 0.25f * fv[0], hv4[1] + 0.25f * fv[1],
                             hv4[2] + 0.25f * fv[2], hv4[3] + 0.25f * fv[3]);
                if ((unsigned)c < 16u && (unsigned)r < 32u) {
                    // k1 = 4*(s1c - h); P = k1 + 2*k2
                    const int off = base + ((y0 + r) << 10) + x0 + fx;
                    st4(out + off,
                        4.0f * (cu[0] - hu4[0]) + 2.0f * fu[0],
                        4.0f * (cu[1] - hu4[1]) + 2.0f * fu[1],
                        4.0f * (cu[2] - hu4[2]) + 2.0f * fu[2],
                        4.0f * (cu[3] - hu4[3]) + 2.0f * fu[3]);
                    st4(out + off + HW,
                        4.0f * (cv[0] - hv4[0]) + 2.0f * fv[0],
                        4.0f * (cv[1] - hv4[1]) + 2.0f * fv[1],
                        4.0f * (cv[2] - hv4[2]) + 2.0f * fv[2],
                        4.0f * (cv[3] - hv4[3]) + 2.0f * fv[3]);
                }
            });
    }
    __syncthreads();

    // ===== stage 3: k3 from s2(B); s3 = h + 0.5*k3 -> A storage (C layout)
    //        (18 cols -1..16, rows -2..33; 12 chunks h=3, 216 thr)
    if (tid < 216) {
        const int cc = tid % 18;
        const int ch = tid / 18;
        const int fx = 4 * (cc - 1);
        const int r0 = -2 + 3 * ch;
        const SL blu{uB, PB, 4, 8};
        const SL blv{vB, PB, 4, 8};
        sweep_col<3>(blu, blv, fx, r0, p,
            [&](int r, const float fu[4], const float fv[4],
                const float cu[4], const float cv[4]) {
                float hu4[4], hv4[4];
                put4(hu4, glu.ld16(r, fx));
                put4(hv4, glv.ld16(r, fx));
                const int ix = (r + 2) * PC + fx + 4;
                st4(uA + ix, hu4[0] + 0.5f * fu[0], hu4[1] + 0.5f * fu[1],
                             hu4[2] + 0.5f * fu[2], hu4[3] + 0.5f * fu[3]);
                st4(vA + ix, hv4[0] + 0.5f * fv[0], hv4[1] + 0.5f * fv[1],
                             hv4[2] + 0.5f * fv[2], hv4[3] + 0.5f * fv[3]);
            });
    }
    __syncthreads();

    // ===== stage 4: k4 from s3(C); out = h + (DT/6)*(P + 2*k3 + k4)
    //        (16 cols 0..15, rows 0..31; 16 chunks h=2, 256 thr)
    {
        const int cc = tid & 15;
        const int ch = tid >> 4;
        const int fx = 4 * cc;
        const int r0 = 2 * ch;
        const SL clu{uA, PC, 2, 4};
        const SL clv{vA, PC, 2, 4};
        const float w6 = 0.5f / 6.0f;
        sweep_col<2>(clu, clv, fx, r0, p,
            [&](int r, const float fu[4], const float fv[4],
                const float cu[4], const float cv[4]) {
                float hu4[4], hv4[4];
                put4(hu4, glu.ld16(r, fx));
                put4(hv4, glv.ld16(r, fx));
                const int off = base + ((y0 + r) << 10) + x0 + fx;
                float Pu[4], Pv[4];
                put4(Pu, ld4(out + off));
                put4(Pv, ld4(out + off + HW));
                // 2*k3 = 4*(s3c - h)
                st4(out + off,
                    hu4[0] + w6 * (Pu[0] + 4.0f * (cu[0] - hu4[0]) + fu[0]),
                    hu4[1] + w6 * (Pu[1] + 4.0f * (cu[1] - hu4[1]) + fu[1]),
                    hu4[2] + w6 * (Pu[2] + 4.0f * (cu[2] - hu4[2]) + fu[2]),
                    hu4[3] + w6 * (Pu[3] + 4.0f * (cu[3] - hu4[3]) + fu[3]));
                st4(out + off + HW,
                    hv4[0] + w6 * (Pv[0] + 4.0f * (cv[0] - hv4[0]) + fv[0]),
                    hv4[1] + w6 * (Pv[1] + 4.0f * (cv[1] - hv4[1]) + fv[1]),
                    hv4[2] + w6 * (Pv[2] + 4.0f * (cv[2] - hv4[2]) + fv[2]),
                    hv4[3] + w6 * (Pv[3] + 4.0f * (cv[3] - hv4[3]) + fv[3]));
            });
    }
}

extern "C" void kernel_launch(void* const* d_in, const int* in_sizes, int n_in,
                              void* d_out, int out_size)
{
    const float* h = nullptr;
    const float* sc[5] = {nullptr, nullptr, nullptr, nullptr, nullptr};
    int nsc = 0;
    for (int i = 0; i < n_in; i++) {
        if (in_sizes[i] == NB * 2 * HW) {
            h = (const float*)d_in[i];
        } else if (nsc < 5) {
            sc[nsc++] = (const float*)d_in[i];
        }
    }
    const float* Re = sc[0];
    const float* UA = sc[1];
    const float* UB = sc[2];
    const float* VA = sc[3];
    const float* VB = sc[4];

    static bool attr_done = false;
    if (!attr_done) {
        cudaFuncSetAttribute(rk4_fused_kernel,
                             cudaFuncAttributeMaxDynamicSharedMemorySize, SMEM_BYTES);
        attr_done = true;
    }

    dim3 grid(1024 / TX, 1024 / TY, NB);    // 16 x 32 x 8 = 4096 blocks
    rk4_fused_kernel<<<grid, 256, SMEM_BYTES>>>(h, (float*)d_out, Re, UA, UB, VA, VB);
    (void)out_size;
}